// round 15
// baseline (speedup 1.0000x reference)
#include <cuda_runtime.h>
#include <cuda.h>
#include <math.h>
#include <stdint.h>

// ---------------- problem constants ----------------
#define T_SEQ      2048
#define HIDDEN     4096
#define NUM_HEADS  32
#define HEAD_DIM   128
#define KV_GROUPS  2
#define Q_SZ       (NUM_HEADS * HEAD_DIM)              // 4096
#define KV_SZ      (KV_GROUPS * HEAD_DIM)              // 256
#define QKV_DIM    (Q_SZ + 2 * KV_SZ)                  // 4608
#define GQA_REP    (NUM_HEADS / KV_GROUPS)             // 16
#define K2DIM      (HIDDEN / 2)                        // 2048 k-pairs

// ---------------- scratch (static device memory; no allocs allowed) ----
__device__ float    g_qkv [(size_t)T_SEQ * QKV_DIM];    // 37.7 MB
__device__ float    g_arnd[(size_t)T_SEQ * HIDDEN];     // rounded hidden (tf32)
__device__ float    g_bt  [(size_t)QKV_DIM * HIDDEN];   // w_qkv^T (tf32)
__device__ uint32_t g_ahi [(size_t)T_SEQ * K2DIM];      // ctx hi plane
__device__ uint32_t g_alo [(size_t)T_SEQ * K2DIM];      // ctx lo plane
__device__ uint32_t g_bhi2[(size_t)HIDDEN * K2DIM];     // w_dense planes
__device__ uint32_t g_blo2[(size_t)HIDDEN * K2DIM];

// =======================================================================
// helpers
// =======================================================================
__device__ __forceinline__ uint32_t smem_u32(const void* p) {
    uint32_t a;
    asm("{ .reg .u64 t; cvta.to.shared.u64 t, %1; cvt.u32.u64 %0, t; }"
        : "=r"(a) : "l"(p));
    return a;
}
__device__ __forceinline__ float f_tf32(float x) {
    uint32_t r;
    asm("cvt.rna.tf32.f32 %0, %1;" : "=r"(r) : "f"(x));
    return __uint_as_float(r);
}
__device__ __forceinline__ float4 f4_tf32(float4 v) {
    v.x = f_tf32(v.x); v.y = f_tf32(v.y);
    v.z = f_tf32(v.z); v.w = f_tf32(v.w);
    return v;
}
__device__ __forceinline__ void bsplit(float x0, float x1,
                                       uint32_t& hi, uint32_t& lo) {
    uint32_t h;
    asm("cvt.rn.bf16x2.f32 %0, %1, %2;" : "=r"(h) : "f"(x1), "f"(x0));
    const float h0 = __uint_as_float(h << 16);
    const float h1 = __uint_as_float(h & 0xffff0000u);
    asm("cvt.rn.bf16x2.f32 %0, %1, %2;" : "=r"(lo) : "f"(x1 - h1), "f"(x0 - h0));
    hi = h;
}
__device__ __forceinline__ void ldsm4(uint32_t* f, uint32_t addr) {
    asm volatile("ldmatrix.sync.aligned.m8n8.x4.shared.b16 {%0,%1,%2,%3}, [%4];"
                 : "=r"(f[0]), "=r"(f[1]), "=r"(f[2]), "=r"(f[3]) : "r"(addr));
}
__device__ __forceinline__ uint32_t sw128(uint32_t off) {
    return off ^ ((off >> 3) & 0x70);
}
__device__ __forceinline__ void cp16(uint32_t dst, const void* src) {
    asm volatile("cp.async.cg.shared.global [%0], [%1], 16;"
                 :: "r"(dst), "l"(src));
}
__device__ __forceinline__ void cp_commit() {
    asm volatile("cp.async.commit_group;" ::: "memory");
}
template <int NREM> __device__ __forceinline__ void cp_wait() {
    asm volatile("cp.async.wait_group %0;" :: "n"(NREM) : "memory");
}
__device__ __forceinline__ void mbar_init(uint32_t a, uint32_t cnt) {
    asm volatile("mbarrier.init.shared.b64 [%0], %1;" :: "r"(a), "r"(cnt) : "memory");
}
__device__ __forceinline__ void mbar_expect_tx(uint32_t a, uint32_t bytes) {
    asm volatile("mbarrier.arrive.expect_tx.shared.b64 _, [%0], %1;"
                 :: "r"(a), "r"(bytes) : "memory");
}
__device__ __forceinline__ void mbar_arrive(uint32_t a) {
    asm volatile("mbarrier.arrive.shared.b64 _, [%0];" :: "r"(a) : "memory");
}
__device__ __forceinline__ void mbar_wait(uint32_t a, uint32_t parity) {
    asm volatile(
        "{\n\t.reg .pred P;\n\t"
        "W_%=:\n\t"
        "mbarrier.try_wait.parity.shared.b64 P, [%0], %1;\n\t"
        "@!P bra W_%=;\n\t}"
        :: "r"(a), "r"(parity) : "memory");
}
__device__ __forceinline__ void tma2d(uint32_t dst, const CUtensorMap* m,
                                      int x, int y, uint32_t mbar) {
    asm volatile(
        "cp.async.bulk.tensor.2d.shared::cta.global.tile.mbarrier::complete_tx::bytes "
        "[%0], [%1, {%2, %3}], [%4];"
        :: "r"(dst), "l"(m), "r"(x), "r"(y), "r"(mbar) : "memory");
}

#define MMA_TF32(d, a0, a1, a2, a3, b0, b1)                                   \
    asm volatile(                                                             \
        "mma.sync.aligned.m16n8k8.row.col.f32.tf32.tf32.f32 "                 \
        "{%0,%1,%2,%3}, {%4,%5,%6,%7}, {%8,%9}, {%0,%1,%2,%3};"               \
        : "+f"((d)[0]), "+f"((d)[1]), "+f"((d)[2]), "+f"((d)[3])              \
        : "r"(a0), "r"(a1), "r"(a2), "r"(a3), "r"(b0), "r"(b1))

#define MMA_BF16(d, a0, a1, a2, a3, b0, b1)                                   \
    asm volatile(                                                             \
        "mma.sync.aligned.m16n8k16.row.col.f32.bf16.bf16.f32 "                \
        "{%0,%1,%2,%3}, {%4,%5,%6,%7}, {%8,%9}, {%0,%1,%2,%3};"               \
        : "+f"((d)[0]), "+f"((d)[1]), "+f"((d)[2]), "+f"((d)[3])              \
        : "r"(a0), "r"(a1), "r"(a2), "r"(a3), "r"(b0), "r"(b1))

// =======================================================================
// prep passes
// =======================================================================
__global__ void round_copy(const float4* __restrict__ src,
                           float4* __restrict__ dst, int total4)
{
    const int i = blockIdx.x * blockDim.x + threadIdx.x;
    if (i >= total4) return;
    dst[i] = f4_tf32(src[i]);
}
__global__ void round_inplace(float4* __restrict__ p, int total4)
{
    const int i = blockIdx.x * blockDim.x + threadIdx.x;
    if (i >= total4) return;
    p[i] = f4_tf32(p[i]);
}
// Bt[n][k] = tf32(B[k][n]); B is [K,N] row-major.
__global__ void transpose_round(const float* __restrict__ B,
                                float* __restrict__ Bt, int K, int N)
{
    __shared__ float tile[32][33];
    const int n0 = blockIdx.x * 32, k0 = blockIdx.y * 32;
    const int tx = threadIdx.x, ty = threadIdx.y;   // 32 x 8
    #pragma unroll
    for (int i = 0; i < 4; ++i)
        tile[ty + 8 * i][tx] = B[(size_t)(k0 + ty + 8 * i) * N + n0 + tx];
    __syncthreads();
    #pragma unroll
    for (int i = 0; i < 4; ++i)
        Bt[(size_t)(n0 + ty + 8 * i) * K + k0 + tx] = f_tf32(tile[tx][ty + 8 * i]);
}
// bf16 hi/lo planes of B^T (k-pair packed) for the dense GEMM.
__global__ void split_bmat_t(const float* __restrict__ B,
                             uint32_t* __restrict__ hiT,
                             uint32_t* __restrict__ loT, int K2, int N)
{
    __shared__ uint32_t th[32][33], tl[32][33];
    const int n0 = blockIdx.x * 32, k20 = blockIdx.y * 32;
    const int tx = threadIdx.x, ty = threadIdx.y;
    #pragma unroll
    for (int i = 0; i < 4; ++i) {
        const int k2 = ty + 8 * i;
        const float x0 = B[(size_t)(2 * (k20 + k2)) * N + n0 + tx];
        const float x1 = B[(size_t)(2 * (k20 + k2) + 1) * N + n0 + tx];
        uint32_t h, l;
        bsplit(x0, x1, h, l);
        th[k2][tx] = h;
        tl[k2][tx] = l;
    }
    __syncthreads();
    #pragma unroll
    for (int i = 0; i < 4; ++i) {
        const int n = ty + 8 * i;
        hiT[(size_t)(n0 + n) * K2 + k20 + tx] = th[tx][n];
        loT[(size_t)(n0 + n) * K2 + k20 + tx] = tl[tx][n];
    }
}

// =======================================================================
// common GEMM geometry: CTA 128x256, 512 threads, warp tile 64x32,
// K-slab 64 elements, 2-stage TMA pipeline. STAGE = 96 KB either way.
// =======================================================================
#define NS        2
#define STAGE_B   98304
#define GEMM_SMEM (NS * STAGE_B + 64)
#define KT_SLABS  64

// ---------------- tf32 GEMM (QKV): A[M,K]@Bt[N,K]^T + bias ------------
__global__ void __launch_bounds__(512)
gemm_tf32(const __grid_constant__ CUtensorMap mA,
          const __grid_constant__ CUtensorMap mB,
          const float* __restrict__ bias, float* __restrict__ C, int N)
{
    extern __shared__ __align__(1024) uint32_t smw[];
    const uint32_t sbase = smem_u32(smw);
    const uint32_t full0  = sbase + NS * STAGE_B;
    const uint32_t empty0 = full0 + 16;

    const int tid  = threadIdx.x;
    const int lane = tid & 31;
    const int wid  = tid >> 5;
    const int wm   = (wid & 1) * 64;
    const int wn   = (wid >> 1) * 32;
    const int r    = lane >> 2;
    const int c    = lane & 3;
    const int mBase = blockIdx.y * 128;
    const int nBase = blockIdx.x * 256;

    const int arow = ((lane >> 3) & 1) * 8 + (lane & 7);
    const int achk = (lane >> 4) * 16;
    const int brow = ((lane >> 4) & 1) * 8 + (lane & 7);
    const int bchk = ((lane >> 3) & 1) * 16;

    if (tid == 0) {
        #pragma unroll
        for (int s = 0; s < NS; ++s) {
            mbar_init(full0 + 8 * s, 1);
            mbar_init(empty0 + 8 * s, 16);
        }
    }
    __syncthreads();

    auto issue_slab = [&](int s, int kt) {
        const uint32_t st = sbase + (uint32_t)s * STAGE_B;
        const uint32_t fb = full0 + 8 * s;
        mbar_expect_tx(fb, STAGE_B);
        #pragma unroll
        for (int kb = 0; kb < 2; ++kb) {
            const int x = kt * 64 + kb * 32;
            tma2d(st + kb * 16384, &mA, x, mBase, fb);
            tma2d(st + 32768 + (2 * kb + 0) * 16384, &mB, x, nBase, fb);
            tma2d(st + 32768 + (2 * kb + 1) * 16384, &mB, x, nBase + 128, fb);
        }
    };

    if (tid == 0) issue_slab(0, 0);

    float acc[4][4][4];
    #pragma unroll
    for (int mi = 0; mi < 4; ++mi)
        #pragma unroll
        for (int ni = 0; ni < 4; ++ni)
            #pragma unroll
            for (int q = 0; q < 4; ++q) acc[mi][ni][q] = 0.f;

    const int nboxp = wn >> 7;
    const int nin   = wn & 127;

    for (int kt = 0; kt < KT_SLABS; ++kt) {
        const int s = kt & 1;
        if (tid == 0) {
            const int nk = kt + 1;
            if (nk < KT_SLABS) {
                if (nk >= NS) mbar_wait(empty0 + 8 * (nk & 1), (nk / NS - 1) & 1);
                issue_slab(nk & 1, nk);
            }
        }
        mbar_wait(full0 + 8 * s, (kt / NS) & 1);

        const uint32_t stg = sbase + (uint32_t)s * STAGE_B;
        #pragma unroll
        for (int kb = 0; kb < 2; ++kb) {
            const uint32_t abox = stg + kb * 16384;
            const uint32_t bbox = stg + 32768 + (2 * kb + nboxp) * 16384;
            #pragma unroll
            for (int t = 0; t < 4; ++t) {
                uint32_t af[4][4];
                #pragma unroll
                for (int mi = 0; mi < 4; ++mi)
                    ldsm4(af[mi], abox +
                          sw128((uint32_t)((wm + mi * 16 + arow) * 128 +
                                           t * 32 + achk)));
                #pragma unroll
                for (int jj = 0; jj < 2; ++jj) {
                    uint32_t bm[4];
                    ldsm4(bm, bbox +
                          sw128((uint32_t)((nin + 16 * jj + brow) * 128 +
                                           t * 32 + bchk)));
                    #pragma unroll
                    for (int mi = 0; mi < 4; ++mi) {
                        MMA_TF32(acc[mi][2 * jj],     af[mi][0], af[mi][1],
                                 af[mi][2], af[mi][3], bm[0], bm[1]);
                        MMA_TF32(acc[mi][2 * jj + 1], af[mi][0], af[mi][1],
                                 af[mi][2], af[mi][3], bm[2], bm[3]);
                    }
                }
            }
        }
        __syncwarp();
        if (lane == 0) mbar_arrive(empty0 + 8 * s);
    }

    #pragma unroll
    for (int mi = 0; mi < 4; ++mi) {
        const int row0 = mBase + wm + mi * 16 + r;
        #pragma unroll
        for (int ni = 0; ni < 4; ++ni) {
            const int col = nBase + wn + ni * 8 + c * 2;
            float2 v0 = make_float2(acc[mi][ni][0], acc[mi][ni][1]);
            float2 v1 = make_float2(acc[mi][ni][2], acc[mi][ni][3]);
            const float2 bb = *(const float2*)&bias[col];
            v0.x += bb.x; v0.y += bb.y;
            v1.x += bb.x; v1.y += bb.y;
            *(float2*)&C[(size_t)row0 * N + col] = v0;
            *(float2*)&C[(size_t)(row0 + 8) * N + col] = v1;
        }
    }
}

// ---------------- bf16x3 GEMM (dense), unchanged -----------------------
#define PLANE_A   16384
#define PLANE_BB  32768

__global__ void __launch_bounds__(512)
gemm_bf16x3(const __grid_constant__ CUtensorMap mAhi,
            const __grid_constant__ CUtensorMap mAlo,
            const __grid_constant__ CUtensorMap mBhi,
            const __grid_constant__ CUtensorMap mBlo,
            float* __restrict__ C, int N)
{
    extern __shared__ __align__(1024) uint32_t smw[];
    const uint32_t sbase = smem_u32(smw);
    const uint32_t full0  = sbase + NS * STAGE_B;
    const uint32_t empty0 = full0 + 16;

    const int tid  = threadIdx.x;
    const int lane = tid & 31;
    const int wid  = tid >> 5;
    const int wm   = (wid & 1) * 64;
    const int wn   = (wid >> 1) * 32;
    const int r    = lane >> 2;
    const int c    = lane & 3;
    const int mBase = blockIdx.y * 128;
    const int nBase = blockIdx.x * 256;

    const int arow = ((lane >> 3) & 1) * 8 + (lane & 7);
    const int achk = (lane >> 4) * 16;
    const int brow = ((lane >> 3) & 2) * 4 + (lane & 7);
    const int bchk = ((lane >> 3) & 1) * 16;

    if (tid == 0) {
        #pragma unroll
        for (int s = 0; s < NS; ++s) {
            mbar_init(full0 + 8 * s, 1);
            mbar_init(empty0 + 8 * s, 16);
        }
    }
    __syncthreads();

    auto issue_slab = [&](int s, int kt) {
        const uint32_t st = sbase + (uint32_t)s * STAGE_B;
        const uint32_t fb = full0 + 8 * s;
        mbar_expect_tx(fb, STAGE_B);
        tma2d(st,                          &mAhi, kt * 32, mBase, fb);
        tma2d(st + PLANE_A,                &mAlo, kt * 32, mBase, fb);
        tma2d(st + 2 * PLANE_A,            &mBhi, kt * 32, nBase, fb);
        tma2d(st + 2 * PLANE_A + 16384,    &mBhi, kt * 32, nBase + 128, fb);
        tma2d(st + 2 * PLANE_A + PLANE_BB, &mBlo, kt * 32, nBase, fb);
        tma2d(st + 2 * PLANE_A + PLANE_BB + 16384,
              &mBlo, kt * 32, nBase + 128, fb);
    };

    if (tid == 0) issue_slab(0, 0);

    float acc[4][4][4];
    #pragma unroll
    for (int mi = 0; mi < 4; ++mi)
        #pragma unroll
        for (int ni = 0; ni < 4; ++ni)
            #pragma unroll
            for (int q = 0; q < 4; ++q) acc[mi][ni][q] = 0.f;

    for (int kt = 0; kt < KT_SLABS; ++kt) {
        const int s = kt & 1;
        if (tid == 0) {
            const int nk = kt + 1;
            if (nk < KT_SLABS) {
                if (nk >= NS) mbar_wait(empty0 + 8 * (nk & 1), (nk / NS - 1) & 1);
                issue_slab(nk & 1, nk);
            }
        }
        mbar_wait(full0 + 8 * s, (kt / NS) & 1);

        const uint32_t stg = sbase + (uint32_t)s * STAGE_B;
        #pragma unroll
        for (int t = 0; t < 4; ++t) {
            uint32_t afh[4][4], afl[4][4];
            #pragma unroll
            for (int mi = 0; mi < 4; ++mi) {
                const uint32_t a = stg +
                    sw128((uint32_t)((wm + mi * 16 + arow) * 128 + t * 32 + achk));
                ldsm4(afh[mi], a);
                ldsm4(afl[mi], a + PLANE_A);
            }
            uint32_t bfh[4][2], bfl[4][2];
            #pragma unroll
            for (int p = 0; p < 2; ++p) {
                const uint32_t b = stg + 2 * PLANE_A +
                    sw128((uint32_t)((wn + p * 16 + brow) * 128 + t * 32 + bchk));
                uint32_t tm[4];
                ldsm4(tm, b);
                bfh[2 * p][0] = tm[0]; bfh[2 * p][1] = tm[1];
                bfh[2 * p + 1][0] = tm[2]; bfh[2 * p + 1][1] = tm[3];
                ldsm4(tm, b + PLANE_BB);
                bfl[2 * p][0] = tm[0]; bfl[2 * p][1] = tm[1];
                bfl[2 * p + 1][0] = tm[2]; bfl[2 * p + 1][1] = tm[3];
            }
            #pragma unroll
            for (int ni = 0; ni < 4; ++ni)
                #pragma unroll
                for (int mi = 0; mi < 4; ++mi) {
                    MMA_BF16(acc[mi][ni], afh[mi][0], afh[mi][1], afh[mi][2],
                             afh[mi][3], bfh[ni][0], bfh[ni][1]);
                    MMA_BF16(acc[mi][ni], afh[mi][0], afh[mi][1], afh[mi][2],
                             afh[mi][3], bfl[ni][0], bfl[ni][1]);
                    MMA_BF16(acc[mi][ni], afl[mi][0], afl[mi][1], afl[mi][2],
                             afl[mi][3], bfh[ni][0], bfh[ni][1]);
                }
        }
        __syncwarp();
        if (lane == 0) mbar_arrive(empty0 + 8 * s);
    }

    #pragma unroll
    for (int mi = 0; mi < 4; ++mi) {
        const int row0 = mBase + wm + mi * 16 + r;
        #pragma unroll
        for (int ni = 0; ni < 4; ++ni) {
            const int col = nBase + wn + ni * 8 + c * 2;
            *(float2*)&C[(size_t)row0 * N + col] =
                make_float2(acc[mi][ni][0], acc[mi][ni][1]);
            *(float2*)&C[(size_t)(row0 + 8) * N + col] =
                make_float2(acc[mi][ni][2], acc[mi][ni][3]);
        }
    }
}

// =======================================================================
// RoPE (interleaved pairs), in-place on Q and K slices of g_qkv.
// =======================================================================
__global__ void rope_kernel(const int* __restrict__ positions)
{
    const int totalQ = T_SEQ * NUM_HEADS * 32;
    const int totalK = T_SEQ * KV_GROUPS * 32;
    int idx = blockIdx.x * blockDim.x + threadIdx.x;

    int t, p, col0;
    if (idx < totalQ) {
        p = idx & 31;
        int h = (idx >> 5) & (NUM_HEADS - 1);
        t = idx >> 10;
        col0 = h * HEAD_DIM + 2 * p;
    } else {
        int rr = idx - totalQ;
        if (rr >= totalK) return;
        p = rr & 31;
        int g = (rr >> 5) & (KV_GROUPS - 1);
        t = rr >> 6;
        col0 = Q_SZ + g * HEAD_DIM + 2 * p;
    }

    const float pos   = (float)positions[t];
    const float theta = powf(10000.0f, -(float)p * (1.0f / 32.0f));
    float sn, cs;
    sincosf(pos * theta, &sn, &cs);

    float* b = g_qkv + (size_t)t * QKV_DIM + col0;
    const float x0 = b[0], x1 = b[1];
    b[0] = x0 * cs - x1 * sn;
    b[1] = x1 * cs + x0 * sn;
}

// =======================================================================
// Flash attention, tf32 mma.sync, kv-block 128 (halved iteration count).
// g_qkv is PRE-ROUNDED to tf32, so K fills via cp.async and the softmax
// folds the 1/sqrt(d) scale post-MMA. P stays in registers (permutation
// trick, k-range doubled); VT rows 512 B with XOR swizzle. Single K/VT
// buffer, 2 syncthreads per iteration, LPT launch order.
// =======================================================================
#define ABM 128
#define ABN2 128
#define AQ_BYTES  (ABM * 528)                // 67584
#define AK_BYTES  (ABN2 * 528)               // 67584
#define AVT_BYTES (HEAD_DIM * ABN2 * 4)      // 65536
#define ATTN_SMEM (AQ_BYTES + AK_BYTES + AVT_BYTES)   // 200704

__global__ __launch_bounds__(256)
void attn_tc(uint32_t* __restrict__ chi, uint32_t* __restrict__ clo)
{
    extern __shared__ __align__(1024) char sraw[];
    const uint32_t sb    = smem_u32(sraw);
    const uint32_t qb    = sb;
    const uint32_t kbuf  = sb + AQ_BYTES;
    const uint32_t vtbuf = kbuf + AK_BYTES;

    const int head = blockIdx.x;
    const int mb   = gridDim.y - 1 - blockIdx.y;   // LPT: heavy blocks first
    const int tid  = threadIdx.x;
    const int lane = tid & 31;
    const int wid  = tid >> 5;
    const int r    = lane >> 2;
    const int c    = lane & 3;
    const int rb   = wid * 16;
    const int g    = head / GQA_REP;
    const float scale = 0.08838834764831845f;      // 1/sqrt(128)

    const int lrow = ((lane >> 3) & 1) * 8 + (lane & 7);
    const int lchk = (lane >> 4) * 16;
    const int brow = ((lane >> 4) & 1) * 8 + (lane & 7);
    const int bchk = ((lane >> 3) & 1) * 16;

    // ---- Q tile (pre-rounded, unscaled) ----
    for (int i = tid; i < ABM * 32; i += 256) {
        const int row = i >> 5, c4 = (i & 31) << 2;
        const float4 v = *(const float4*)&g_qkv[(size_t)(mb * ABM + row) *
                                                QKV_DIM + head * HEAD_DIM + c4];
        *(float4*)(sraw + (size_t)row * 528 + c4 * 4) = v;
    }

    float o[16][4];
    #pragma unroll
    for (int j = 0; j < 16; ++j)
        #pragma unroll
        for (int q = 0; q < 4; ++q) o[j][q] = 0.f;
    float mst0 = -1e30f, mst1 = -1e30f, lst0 = 0.f, lst1 = 0.f;

    for (int nb = 0; nb <= mb; ++nb) {
        __syncthreads();                         // prev iter's reads done

        // ---- K fill via cp.async (pre-rounded gmem) ----
        #pragma unroll
        for (int u = 0; u < 16; ++u) {
            const int i = tid + 256 * u;
            const int row = i >> 5, ch = i & 31;
            cp16(kbuf + (uint32_t)(row * 528 + ch * 16),
                 g_qkv + (size_t)(nb * ABN2 + row) * QKV_DIM + Q_SZ +
                     g * HEAD_DIM + ch * 4);
        }
        cp_commit();

        // ---- V gather (permuted) -> VT ----
        #pragma unroll 4
        for (int u = 0; u < 16; ++u) {
            const int i = tid + 256 * u;
            const int d = i & 127, idx = i >> 7, m = idx >> 1, h2 = idx & 1;
            const float* vb = g_qkv + (size_t)(nb * ABN2) * QKV_DIM + Q_SZ +
                              KV_SZ + g * HEAD_DIM + d;
            float4 v;
            v.x = vb[(size_t)(8 * m + h2 + 0) * QKV_DIM];
            v.y = vb[(size_t)(8 * m + h2 + 2) * QKV_DIM];
            v.z = vb[(size_t)(8 * m + h2 + 4) * QKV_DIM];
            v.w = vb[(size_t)(8 * m + h2 + 6) * QKV_DIM];
            const uint32_t off = (uint32_t)d * 512 +
                (((uint32_t)(32 * m + 16 * h2)) ^ (((uint32_t)d & 7) << 4));
            *(float4*)(sraw + (AQ_BYTES + AK_BYTES) + off) = v;
        }

        cp_wait<0>();
        __syncthreads();                         // K + V tiles ready

        // ---- S = Q K^T (raw, unscaled) ----
        float s[16][4];
        #pragma unroll
        for (int j = 0; j < 16; ++j)
            #pragma unroll
            for (int q = 0; q < 4; ++q) s[j][q] = 0.f;

        #pragma unroll 2
        for (int k0 = 0; k0 < 16; ++k0) {
            uint32_t aq[4];
            ldsm4(aq, qb + (uint32_t)((rb + lrow) * 132 + 8 * k0) * 4 + lchk);
            #pragma unroll
            for (int jp = 0; jp < 8; ++jp) {
                uint32_t kf[4];
                ldsm4(kf, kbuf + (uint32_t)((16 * jp + brow) * 132 +
                                            8 * k0) * 4 + bchk);
                MMA_TF32(s[2 * jp],     aq[0], aq[1], aq[2], aq[3], kf[0], kf[1]);
                MMA_TF32(s[2 * jp + 1], aq[0], aq[1], aq[2], aq[3], kf[2], kf[3]);
            }
        }

        // ---- causal mask (diagonal block only) ----
        if (nb == mb) {
            const int row0 = mb * ABM + rb + r;
            #pragma unroll
            for (int j = 0; j < 16; ++j) {
                const int col = nb * ABN2 + 8 * j + 2 * c;
                if (col     > row0)     s[j][0] = -1e30f;
                if (col + 1 > row0)     s[j][1] = -1e30f;
                if (col     > row0 + 8) s[j][2] = -1e30f;
                if (col + 1 > row0 + 8) s[j][3] = -1e30f;
            }
        }

        // ---- online softmax (scale folded here; scale > 0) ----
        float mx0 = -1e30f, mx1 = -1e30f;
        #pragma unroll
        for (int j = 0; j < 16; ++j) {
            mx0 = fmaxf(mx0, fmaxf(s[j][0], s[j][1]));
            mx1 = fmaxf(mx1, fmaxf(s[j][2], s[j][3]));
        }
        mx0 = fmaxf(mx0, __shfl_xor_sync(0xffffffffu, mx0, 1));
        mx0 = fmaxf(mx0, __shfl_xor_sync(0xffffffffu, mx0, 2));
        mx1 = fmaxf(mx1, __shfl_xor_sync(0xffffffffu, mx1, 1));
        mx1 = fmaxf(mx1, __shfl_xor_sync(0xffffffffu, mx1, 2));
        const float mn0 = fmaxf(mst0, scale * mx0);
        const float mn1 = fmaxf(mst1, scale * mx1);
        const float al0 = __expf(mst0 - mn0), al1 = __expf(mst1 - mn1);
        float sum0 = 0.f, sum1 = 0.f;
        #pragma unroll
        for (int j = 0; j < 16; ++j) {
            s[j][0] = f_tf32(__expf(fmaf(scale, s[j][0], -mn0))); sum0 += s[j][0];
            s[j][1] = f_tf32(__expf(fmaf(scale, s[j][1], -mn0))); sum0 += s[j][1];
            s[j][2] = f_tf32(__expf(fmaf(scale, s[j][2], -mn1))); sum1 += s[j][2];
            s[j][3] = f_tf32(__expf(fmaf(scale, s[j][3], -mn1))); sum1 += s[j][3];
        }
        sum0 += __shfl_xor_sync(0xffffffffu, sum0, 1);
        sum0 += __shfl_xor_sync(0xffffffffu, sum0, 2);
        sum1 += __shfl_xor_sync(0xffffffffu, sum1, 1);
        sum1 += __shfl_xor_sync(0xffffffffu, sum1, 2);
        lst0 = lst0 * al0 + sum0;  mst0 = mn0;
        lst1 = lst1 * al1 + sum1;  mst1 = mn1;
        #pragma unroll
        for (int j = 0; j < 16; ++j) {
            o[j][0] *= al0; o[j][1] *= al0;
            o[j][2] *= al1; o[j][3] *= al1;
        }

        // ---- O += P @ V (P from s-regs via permutation; VT pre-permuted) --
        #pragma unroll 2
        for (int kk = 0; kk < 16; ++kk) {
            const uint32_t a0 = __float_as_uint(s[kk][0]);
            const uint32_t a1 = __float_as_uint(s[kk][2]);
            const uint32_t a2 = __float_as_uint(s[kk][1]);
            const uint32_t a3 = __float_as_uint(s[kk][3]);
            #pragma unroll
            for (int jp = 0; jp < 8; ++jp) {
                const int vrow = 16 * jp + brow;
                const uint32_t addr = vtbuf + (uint32_t)vrow * 512 +
                    (((uint32_t)(kk * 32 + bchk)) ^ (((uint32_t)vrow & 7) << 4));
                uint32_t vf[4];
                ldsm4(vf, addr);
                MMA_TF32(o[2 * jp],     a0, a1, a2, a3, vf[0], vf[1]);
                MMA_TF32(o[2 * jp + 1], a0, a1, a2, a3, vf[2], vf[3]);
            }
        }
    }

    // ---- normalize + write ctx as pre-split bf16 hi/lo planes ----
    const float il0 = 1.0f / lst0, il1 = 1.0f / lst1;
    const int trow = mb * ABM + rb + r;
    #pragma unroll
    for (int j = 0; j < 16; ++j) {
        const int col = head * HEAD_DIM + 8 * j + 2 * c;
        uint32_t h, l;
        bsplit(o[j][0] * il0, o[j][1] * il0, h, l);
        const size_t p0 = ((size_t)trow * HIDDEN + col) >> 1;
        chi[p0] = h; clo[p0] = l;
        bsplit(o[j][2] * il1, o[j][3] * il1, h, l);
        const size_t p1 = ((size_t)(trow + 8) * HIDDEN + col) >> 1;
        chi[p1] = h; clo[p1] = l;
    }
}

// =======================================================================
// host side
// =======================================================================
typedef CUresult (*tmap_encode_fn)(
    CUtensorMap*, CUtensorMapDataType, cuuint32_t, void*,
    const cuuint64_t*, const cuuint64_t*, const cuuint32_t*, const cuuint32_t*,
    CUtensorMapInterleave, CUtensorMapSwizzle, CUtensorMapL2promotion,
    CUtensorMapFloatOOBfill);

static tmap_encode_fn get_encoder()
{
    void* p = nullptr;
    cudaDriverEntryPointQueryResult qr;
#if CUDART_VERSION >= 12050
    cudaGetDriverEntryPointByVersion("cuTensorMapEncodeTiled", &p, 12000,
                                     cudaEnableDefault, &qr);
#else
    cudaGetDriverEntryPoint("cuTensorMapEncodeTiled", &p, cudaEnableDefault, &qr);
#endif
    return (tmap_encode_fn)p;
}

static void make_map(tmap_encode_fn enc, CUtensorMap* m, void* ptr,
                     uint64_t inner, uint64_t rows)
{
    cuuint64_t dims[2]    = {inner, rows};
    cuuint64_t strides[1] = {inner * 4};
    cuuint32_t box[2]     = {32, 128};
    cuuint32_t es[2]      = {1, 1};
    enc(m, CU_TENSOR_MAP_DATA_TYPE_FLOAT32, 2, ptr, dims, strides, box, es,
        CU_TENSOR_MAP_INTERLEAVE_NONE, CU_TENSOR_MAP_SWIZZLE_128B,
        CU_TENSOR_MAP_L2_PROMOTION_L2_128B, CU_TENSOR_MAP_FLOAT_OOB_FILL_NONE);
}

extern "C" void kernel_launch(void* const* d_in, const int* in_sizes, int n_in,
                              void* d_out, int out_size)
{
    const int*   positions = (const int*)d_in[0];
    const float* hidden    = (const float*)d_in[1];
    const float* w_qkv     = (const float*)d_in[2];
    const float* b_qkv     = (const float*)d_in[3];
    const float* w_dense   = (const float*)d_in[4];
    float*       out       = (float*)d_out;

    float *qkv_p, *arnd, *bt;
    uint32_t *ahi, *alo, *bhi2, *blo2;
    cudaGetSymbolAddress((void**)&qkv_p, g_qkv);
    cudaGetSymbolAddress((void**)&arnd,  g_arnd);
    cudaGetSymbolAddress((void**)&bt,    g_bt);
    cudaGetSymbolAddress((void**)&ahi,   g_ahi);
    cudaGetSymbolAddress((void**)&alo,   g_alo);
    cudaGetSymbolAddress((void**)&bhi2,  g_bhi2);
    cudaGetSymbolAddress((void**)&blo2,  g_blo2);

    tmap_encode_fn enc = get_encoder();
    CUtensorMap mA, mB, mAhi, mAlo, mBhi2, mBlo2;
    make_map(enc, &mA,    arnd, HIDDEN, T_SEQ);
    make_map(enc, &mB,    bt,   HIDDEN, QKV_DIM);
    make_map(enc, &mAhi,  ahi,  K2DIM,  T_SEQ);
    make_map(enc, &mAlo,  alo,  K2DIM,  T_SEQ);
    make_map(enc, &mBhi2, bhi2, K2DIM,  HIDDEN);
    make_map(enc, &mBlo2, blo2, K2DIM,  HIDDEN);

    cudaFuncSetAttribute(gemm_tf32,
                         cudaFuncAttributeMaxDynamicSharedMemorySize, GEMM_SMEM);
    cudaFuncSetAttribute(gemm_bf16x3,
                         cudaFuncAttributeMaxDynamicSharedMemorySize, GEMM_SMEM);
    cudaFuncSetAttribute(attn_tc,
                         cudaFuncAttributeMaxDynamicSharedMemorySize, ATTN_SMEM);

    // 1) prep passes
    round_copy<<<(T_SEQ * HIDDEN / 4 + 255) / 256, 256>>>(
        (const float4*)hidden, (float4*)arnd, T_SEQ * HIDDEN / 4);
    transpose_round<<<dim3(QKV_DIM / 32, HIDDEN / 32), dim3(32, 8)>>>(
        w_qkv, bt, HIDDEN, QKV_DIM);
    split_bmat_t<<<dim3(HIDDEN / 32, K2DIM / 32), dim3(32, 8)>>>(
        w_dense, bhi2, blo2, K2DIM, HIDDEN);

    // 2) QKV = hidden @ w_qkv + b_qkv   (tf32 tensor cores)
    gemm_tf32<<<dim3(QKV_DIM / 256, T_SEQ / 128), 512, GEMM_SMEM>>>(
        mA, mB, b_qkv, qkv_p, QKV_DIM);

    // 3) RoPE in place, then round all of qkv to tf32 (idempotent)
    const int totalRope = T_SEQ * NUM_HEADS * 32 + T_SEQ * KV_GROUPS * 32;
    rope_kernel<<<(totalRope + 255) / 256, 256>>>(positions);
    round_inplace<<<(T_SEQ * QKV_DIM / 4 + 255) / 256, 256>>>(
        (float4*)qkv_p, T_SEQ * QKV_DIM / 4);

    // 4) attention -> ctx hi/lo planes
    attn_tc<<<dim3(NUM_HEADS, T_SEQ / ABM), 256, ATTN_SMEM>>>(ahi, alo);

    // 5) out = ctx @ w_dense   (bf16x3 tensor cores)
    gemm_bf16x3<<<dim3(HIDDEN / 256, T_SEQ / 128), 512, GEMM_SMEM>>>(
        mAhi, mAlo, mBhi2, mBlo2, out, HIDDEN);
}

// round 16
// speedup vs baseline: 1.1125x; 1.1125x over previous
#include <cuda_runtime.h>
#include <cuda.h>
#include <math.h>
#include <stdint.h>

// ---------------- problem constants ----------------
#define T_SEQ      2048
#define HIDDEN     4096
#define NUM_HEADS  32
#define HEAD_DIM   128
#define KV_GROUPS  2
#define Q_SZ       (NUM_HEADS * HEAD_DIM)              // 4096
#define KV_SZ      (KV_GROUPS * HEAD_DIM)              // 256
#define QKV_DIM    (Q_SZ + 2 * KV_SZ)                  // 4608
#define GQA_REP    (NUM_HEADS / KV_GROUPS)             // 16
#define K2DIM      (HIDDEN / 2)                        // 2048 k-pairs

// ---------------- scratch (static device memory; no allocs allowed) ----
__device__ float    g_qkv [(size_t)T_SEQ * QKV_DIM];    // 37.7 MB
__device__ float    g_arnd[(size_t)T_SEQ * HIDDEN];     // rounded hidden (tf32)
__device__ float    g_bt  [(size_t)QKV_DIM * HIDDEN];   // w_qkv^T (tf32)
__device__ uint32_t g_ahi [(size_t)T_SEQ * K2DIM];      // ctx hi plane
__device__ uint32_t g_alo [(size_t)T_SEQ * K2DIM];      // ctx lo plane
__device__ uint32_t g_bhi2[(size_t)HIDDEN * K2DIM];     // w_dense planes
__device__ uint32_t g_blo2[(size_t)HIDDEN * K2DIM];

// =======================================================================
// helpers
// =======================================================================
__device__ __forceinline__ uint32_t smem_u32(const void* p) {
    uint32_t a;
    asm("{ .reg .u64 t; cvta.to.shared.u64 t, %1; cvt.u32.u64 %0, t; }"
        : "=r"(a) : "l"(p));
    return a;
}
__device__ __forceinline__ float f_tf32(float x) {
    uint32_t r;
    asm("cvt.rna.tf32.f32 %0, %1;" : "=r"(r) : "f"(x));
    return __uint_as_float(r);
}
__device__ __forceinline__ float4 f4_tf32(float4 v) {
    v.x = f_tf32(v.x); v.y = f_tf32(v.y);
    v.z = f_tf32(v.z); v.w = f_tf32(v.w);
    return v;
}
__device__ __forceinline__ void bsplit(float x0, float x1,
                                       uint32_t& hi, uint32_t& lo) {
    uint32_t h;
    asm("cvt.rn.bf16x2.f32 %0, %1, %2;" : "=r"(h) : "f"(x1), "f"(x0));
    const float h0 = __uint_as_float(h << 16);
    const float h1 = __uint_as_float(h & 0xffff0000u);
    asm("cvt.rn.bf16x2.f32 %0, %1, %2;" : "=r"(lo) : "f"(x1 - h1), "f"(x0 - h0));
    hi = h;
}
__device__ __forceinline__ void ldsm4(uint32_t* f, uint32_t addr) {
    asm volatile("ldmatrix.sync.aligned.m8n8.x4.shared.b16 {%0,%1,%2,%3}, [%4];"
                 : "=r"(f[0]), "=r"(f[1]), "=r"(f[2]), "=r"(f[3]) : "r"(addr));
}
__device__ __forceinline__ uint32_t sw128(uint32_t off) {
    return off ^ ((off >> 3) & 0x70);
}
__device__ __forceinline__ void cp16(uint32_t dst, const void* src) {
    asm volatile("cp.async.cg.shared.global [%0], [%1], 16;"
                 :: "r"(dst), "l"(src));
}
__device__ __forceinline__ void cp_commit() {
    asm volatile("cp.async.commit_group;" ::: "memory");
}
template <int NREM> __device__ __forceinline__ void cp_wait() {
    asm volatile("cp.async.wait_group %0;" :: "n"(NREM) : "memory");
}
__device__ __forceinline__ void mbar_init(uint32_t a, uint32_t cnt) {
    asm volatile("mbarrier.init.shared.b64 [%0], %1;" :: "r"(a), "r"(cnt) : "memory");
}
__device__ __forceinline__ void mbar_expect_tx(uint32_t a, uint32_t bytes) {
    asm volatile("mbarrier.arrive.expect_tx.shared.b64 _, [%0], %1;"
                 :: "r"(a), "r"(bytes) : "memory");
}
__device__ __forceinline__ void mbar_arrive(uint32_t a) {
    asm volatile("mbarrier.arrive.shared.b64 _, [%0];" :: "r"(a) : "memory");
}
__device__ __forceinline__ void mbar_wait(uint32_t a, uint32_t parity) {
    asm volatile(
        "{\n\t.reg .pred P;\n\t"
        "W_%=:\n\t"
        "mbarrier.try_wait.parity.shared.b64 P, [%0], %1;\n\t"
        "@!P bra W_%=;\n\t}"
        :: "r"(a), "r"(parity) : "memory");
}
__device__ __forceinline__ void tma2d(uint32_t dst, const CUtensorMap* m,
                                      int x, int y, uint32_t mbar) {
    asm volatile(
        "cp.async.bulk.tensor.2d.shared::cta.global.tile.mbarrier::complete_tx::bytes "
        "[%0], [%1, {%2, %3}], [%4];"
        :: "r"(dst), "l"(m), "r"(x), "r"(y), "r"(mbar) : "memory");
}

#define MMA_TF32(d, a0, a1, a2, a3, b0, b1)                                   \
    asm volatile(                                                             \
        "mma.sync.aligned.m16n8k8.row.col.f32.tf32.tf32.f32 "                 \
        "{%0,%1,%2,%3}, {%4,%5,%6,%7}, {%8,%9}, {%0,%1,%2,%3};"               \
        : "+f"((d)[0]), "+f"((d)[1]), "+f"((d)[2]), "+f"((d)[3])              \
        : "r"(a0), "r"(a1), "r"(a2), "r"(a3), "r"(b0), "r"(b1))

#define MMA_BF16(d, a0, a1, a2, a3, b0, b1)                                   \
    asm volatile(                                                             \
        "mma.sync.aligned.m16n8k16.row.col.f32.bf16.bf16.f32 "                \
        "{%0,%1,%2,%3}, {%4,%5,%6,%7}, {%8,%9}, {%0,%1,%2,%3};"               \
        : "+f"((d)[0]), "+f"((d)[1]), "+f"((d)[2]), "+f"((d)[3])              \
        : "r"(a0), "r"(a1), "r"(a2), "r"(a3), "r"(b0), "r"(b1))

// =======================================================================
// prep passes
// =======================================================================
__global__ void round_copy(const float4* __restrict__ src,
                           float4* __restrict__ dst, int total4)
{
    const int i = blockIdx.x * blockDim.x + threadIdx.x;
    if (i >= total4) return;
    dst[i] = f4_tf32(src[i]);
}
__global__ void round_inplace(float4* __restrict__ p, int total4)
{
    const int i = blockIdx.x * blockDim.x + threadIdx.x;
    if (i >= total4) return;
    p[i] = f4_tf32(p[i]);
}
// Bt[n][k] = tf32(B[k][n]); B is [K,N] row-major.
__global__ void transpose_round(const float* __restrict__ B,
                                float* __restrict__ Bt, int K, int N)
{
    __shared__ float tile[32][33];
    const int n0 = blockIdx.x * 32, k0 = blockIdx.y * 32;
    const int tx = threadIdx.x, ty = threadIdx.y;   // 32 x 8
    #pragma unroll
    for (int i = 0; i < 4; ++i)
        tile[ty + 8 * i][tx] = B[(size_t)(k0 + ty + 8 * i) * N + n0 + tx];
    __syncthreads();
    #pragma unroll
    for (int i = 0; i < 4; ++i)
        Bt[(size_t)(n0 + ty + 8 * i) * K + k0 + tx] = f_tf32(tile[tx][ty + 8 * i]);
}
// bf16 hi/lo planes of B^T (k-pair packed) for the dense GEMM.
__global__ void split_bmat_t(const float* __restrict__ B,
                             uint32_t* __restrict__ hiT,
                             uint32_t* __restrict__ loT, int K2, int N)
{
    __shared__ uint32_t th[32][33], tl[32][33];
    const int n0 = blockIdx.x * 32, k20 = blockIdx.y * 32;
    const int tx = threadIdx.x, ty = threadIdx.y;
    #pragma unroll
    for (int i = 0; i < 4; ++i) {
        const int k2 = ty + 8 * i;
        const float x0 = B[(size_t)(2 * (k20 + k2)) * N + n0 + tx];
        const float x1 = B[(size_t)(2 * (k20 + k2) + 1) * N + n0 + tx];
        uint32_t h, l;
        bsplit(x0, x1, h, l);
        th[k2][tx] = h;
        tl[k2][tx] = l;
    }
    __syncthreads();
    #pragma unroll
    for (int i = 0; i < 4; ++i) {
        const int n = ty + 8 * i;
        hiT[(size_t)(n0 + n) * K2 + k20 + tx] = th[tx][n];
        loT[(size_t)(n0 + n) * K2 + k20 + tx] = tl[tx][n];
    }
}

// =======================================================================
// common GEMM geometry: CTA 128x256, 512 threads, warp tile 64x32,
// K-slab 64 elements, 2-stage TMA pipeline. STAGE = 96 KB either way.
// =======================================================================
#define NS        2
#define STAGE_B   98304
#define GEMM_SMEM (NS * STAGE_B + 64)
#define KT_SLABS  64

// ---------------- tf32 GEMM (QKV): A[M,K]@Bt[N,K]^T + bias ------------
__global__ void __launch_bounds__(512)
gemm_tf32(const __grid_constant__ CUtensorMap mA,
          const __grid_constant__ CUtensorMap mB,
          const float* __restrict__ bias, float* __restrict__ C, int N)
{
    extern __shared__ __align__(1024) uint32_t smw[];
    const uint32_t sbase = smem_u32(smw);
    const uint32_t full0  = sbase + NS * STAGE_B;
    const uint32_t empty0 = full0 + 16;

    const int tid  = threadIdx.x;
    const int lane = tid & 31;
    const int wid  = tid >> 5;
    const int wm   = (wid & 1) * 64;
    const int wn   = (wid >> 1) * 32;
    const int r    = lane >> 2;
    const int c    = lane & 3;
    const int mBase = blockIdx.y * 128;
    const int nBase = blockIdx.x * 256;

    const int arow = ((lane >> 3) & 1) * 8 + (lane & 7);
    const int achk = (lane >> 4) * 16;
    const int brow = ((lane >> 4) & 1) * 8 + (lane & 7);
    const int bchk = ((lane >> 3) & 1) * 16;

    if (tid == 0) {
        #pragma unroll
        for (int s = 0; s < NS; ++s) {
            mbar_init(full0 + 8 * s, 1);
            mbar_init(empty0 + 8 * s, 16);
        }
    }
    __syncthreads();

    auto issue_slab = [&](int s, int kt) {
        const uint32_t st = sbase + (uint32_t)s * STAGE_B;
        const uint32_t fb = full0 + 8 * s;
        mbar_expect_tx(fb, STAGE_B);
        #pragma unroll
        for (int kb = 0; kb < 2; ++kb) {
            const int x = kt * 64 + kb * 32;
            tma2d(st + kb * 16384, &mA, x, mBase, fb);
            tma2d(st + 32768 + (2 * kb + 0) * 16384, &mB, x, nBase, fb);
            tma2d(st + 32768 + (2 * kb + 1) * 16384, &mB, x, nBase + 128, fb);
        }
    };

    if (tid == 0) issue_slab(0, 0);

    float acc[4][4][4];
    #pragma unroll
    for (int mi = 0; mi < 4; ++mi)
        #pragma unroll
        for (int ni = 0; ni < 4; ++ni)
            #pragma unroll
            for (int q = 0; q < 4; ++q) acc[mi][ni][q] = 0.f;

    const int nboxp = wn >> 7;
    const int nin   = wn & 127;

    for (int kt = 0; kt < KT_SLABS; ++kt) {
        const int s = kt & 1;
        if (tid == 0) {
            const int nk = kt + 1;
            if (nk < KT_SLABS) {
                if (nk >= NS) mbar_wait(empty0 + 8 * (nk & 1), (nk / NS - 1) & 1);
                issue_slab(nk & 1, nk);
            }
        }
        mbar_wait(full0 + 8 * s, (kt / NS) & 1);

        const uint32_t stg = sbase + (uint32_t)s * STAGE_B;
        #pragma unroll
        for (int kb = 0; kb < 2; ++kb) {
            const uint32_t abox = stg + kb * 16384;
            const uint32_t bbox = stg + 32768 + (2 * kb + nboxp) * 16384;
            #pragma unroll
            for (int t = 0; t < 4; ++t) {
                uint32_t af[4][4];
                #pragma unroll
                for (int mi = 0; mi < 4; ++mi)
                    ldsm4(af[mi], abox +
                          sw128((uint32_t)((wm + mi * 16 + arow) * 128 +
                                           t * 32 + achk)));
                #pragma unroll
                for (int jj = 0; jj < 2; ++jj) {
                    uint32_t bm[4];
                    ldsm4(bm, bbox +
                          sw128((uint32_t)((nin + 16 * jj + brow) * 128 +
                                           t * 32 + bchk)));
                    #pragma unroll
                    for (int mi = 0; mi < 4; ++mi) {
                        MMA_TF32(acc[mi][2 * jj],     af[mi][0], af[mi][1],
                                 af[mi][2], af[mi][3], bm[0], bm[1]);
                        MMA_TF32(acc[mi][2 * jj + 1], af[mi][0], af[mi][1],
                                 af[mi][2], af[mi][3], bm[2], bm[3]);
                    }
                }
            }
        }
        __syncwarp();
        if (lane == 0) mbar_arrive(empty0 + 8 * s);
    }

    #pragma unroll
    for (int mi = 0; mi < 4; ++mi) {
        const int row0 = mBase + wm + mi * 16 + r;
        #pragma unroll
        for (int ni = 0; ni < 4; ++ni) {
            const int col = nBase + wn + ni * 8 + c * 2;
            float2 v0 = make_float2(acc[mi][ni][0], acc[mi][ni][1]);
            float2 v1 = make_float2(acc[mi][ni][2], acc[mi][ni][3]);
            const float2 bb = *(const float2*)&bias[col];
            v0.x += bb.x; v0.y += bb.y;
            v1.x += bb.x; v1.y += bb.y;
            *(float2*)&C[(size_t)row0 * N + col] = v0;
            *(float2*)&C[(size_t)(row0 + 8) * N + col] = v1;
        }
    }
}

// ---------------- bf16x3 GEMM (dense), unchanged -----------------------
#define PLANE_A   16384
#define PLANE_BB  32768

__global__ void __launch_bounds__(512)
gemm_bf16x3(const __grid_constant__ CUtensorMap mAhi,
            const __grid_constant__ CUtensorMap mAlo,
            const __grid_constant__ CUtensorMap mBhi,
            const __grid_constant__ CUtensorMap mBlo,
            float* __restrict__ C, int N)
{
    extern __shared__ __align__(1024) uint32_t smw[];
    const uint32_t sbase = smem_u32(smw);
    const uint32_t full0  = sbase + NS * STAGE_B;
    const uint32_t empty0 = full0 + 16;

    const int tid  = threadIdx.x;
    const int lane = tid & 31;
    const int wid  = tid >> 5;
    const int wm   = (wid & 1) * 64;
    const int wn   = (wid >> 1) * 32;
    const int r    = lane >> 2;
    const int c    = lane & 3;
    const int mBase = blockIdx.y * 128;
    const int nBase = blockIdx.x * 256;

    const int arow = ((lane >> 3) & 1) * 8 + (lane & 7);
    const int achk = (lane >> 4) * 16;
    const int brow = ((lane >> 3) & 2) * 4 + (lane & 7);
    const int bchk = ((lane >> 3) & 1) * 16;

    if (tid == 0) {
        #pragma unroll
        for (int s = 0; s < NS; ++s) {
            mbar_init(full0 + 8 * s, 1);
            mbar_init(empty0 + 8 * s, 16);
        }
    }
    __syncthreads();

    auto issue_slab = [&](int s, int kt) {
        const uint32_t st = sbase + (uint32_t)s * STAGE_B;
        const uint32_t fb = full0 + 8 * s;
        mbar_expect_tx(fb, STAGE_B);
        tma2d(st,                          &mAhi, kt * 32, mBase, fb);
        tma2d(st + PLANE_A,                &mAlo, kt * 32, mBase, fb);
        tma2d(st + 2 * PLANE_A,            &mBhi, kt * 32, nBase, fb);
        tma2d(st + 2 * PLANE_A + 16384,    &mBhi, kt * 32, nBase + 128, fb);
        tma2d(st + 2 * PLANE_A + PLANE_BB, &mBlo, kt * 32, nBase, fb);
        tma2d(st + 2 * PLANE_A + PLANE_BB + 16384,
              &mBlo, kt * 32, nBase + 128, fb);
    };

    if (tid == 0) issue_slab(0, 0);

    float acc[4][4][4];
    #pragma unroll
    for (int mi = 0; mi < 4; ++mi)
        #pragma unroll
        for (int ni = 0; ni < 4; ++ni)
            #pragma unroll
            for (int q = 0; q < 4; ++q) acc[mi][ni][q] = 0.f;

    for (int kt = 0; kt < KT_SLABS; ++kt) {
        const int s = kt & 1;
        if (tid == 0) {
            const int nk = kt + 1;
            if (nk < KT_SLABS) {
                if (nk >= NS) mbar_wait(empty0 + 8 * (nk & 1), (nk / NS - 1) & 1);
                issue_slab(nk & 1, nk);
            }
        }
        mbar_wait(full0 + 8 * s, (kt / NS) & 1);

        const uint32_t stg = sbase + (uint32_t)s * STAGE_B;
        #pragma unroll
        for (int t = 0; t < 4; ++t) {
            uint32_t afh[4][4], afl[4][4];
            #pragma unroll
            for (int mi = 0; mi < 4; ++mi) {
                const uint32_t a = stg +
                    sw128((uint32_t)((wm + mi * 16 + arow) * 128 + t * 32 + achk));
                ldsm4(afh[mi], a);
                ldsm4(afl[mi], a + PLANE_A);
            }
            uint32_t bfh[4][2], bfl[4][2];
            #pragma unroll
            for (int p = 0; p < 2; ++p) {
                const uint32_t b = stg + 2 * PLANE_A +
                    sw128((uint32_t)((wn + p * 16 + brow) * 128 + t * 32 + bchk));
                uint32_t tm[4];
                ldsm4(tm, b);
                bfh[2 * p][0] = tm[0]; bfh[2 * p][1] = tm[1];
                bfh[2 * p + 1][0] = tm[2]; bfh[2 * p + 1][1] = tm[3];
                ldsm4(tm, b + PLANE_BB);
                bfl[2 * p][0] = tm[0]; bfl[2 * p][1] = tm[1];
                bfl[2 * p + 1][0] = tm[2]; bfl[2 * p + 1][1] = tm[3];
            }
            #pragma unroll
            for (int ni = 0; ni < 4; ++ni)
                #pragma unroll
                for (int mi = 0; mi < 4; ++mi) {
                    MMA_BF16(acc[mi][ni], afh[mi][0], afh[mi][1], afh[mi][2],
                             afh[mi][3], bfh[ni][0], bfh[ni][1]);
                    MMA_BF16(acc[mi][ni], afh[mi][0], afh[mi][1], afh[mi][2],
                             afh[mi][3], bfl[ni][0], bfl[ni][1]);
                    MMA_BF16(acc[mi][ni], afl[mi][0], afl[mi][1], afl[mi][2],
                             afl[mi][3], bfh[ni][0], bfh[ni][1]);
                }
        }
        __syncwarp();
        if (lane == 0) mbar_arrive(empty0 + 8 * s);
    }

    #pragma unroll
    for (int mi = 0; mi < 4; ++mi) {
        const int row0 = mBase + wm + mi * 16 + r;
        #pragma unroll
        for (int ni = 0; ni < 4; ++ni) {
            const int col = nBase + wn + ni * 8 + c * 2;
            *(float2*)&C[(size_t)row0 * N + col] =
                make_float2(acc[mi][ni][0], acc[mi][ni][1]);
            *(float2*)&C[(size_t)(row0 + 8) * N + col] =
                make_float2(acc[mi][ni][2], acc[mi][ni][3]);
        }
    }
}

// =======================================================================
// RoPE (interleaved pairs), in-place on Q and K slices of g_qkv.
// =======================================================================
__global__ void rope_kernel(const int* __restrict__ positions)
{
    const int totalQ = T_SEQ * NUM_HEADS * 32;
    const int totalK = T_SEQ * KV_GROUPS * 32;
    int idx = blockIdx.x * blockDim.x + threadIdx.x;

    int t, p, col0;
    if (idx < totalQ) {
        p = idx & 31;
        int h = (idx >> 5) & (NUM_HEADS - 1);
        t = idx >> 10;
        col0 = h * HEAD_DIM + 2 * p;
    } else {
        int rr = idx - totalQ;
        if (rr >= totalK) return;
        p = rr & 31;
        int g = (rr >> 5) & (KV_GROUPS - 1);
        t = rr >> 6;
        col0 = Q_SZ + g * HEAD_DIM + 2 * p;
    }

    const float pos   = (float)positions[t];
    const float theta = powf(10000.0f, -(float)p * (1.0f / 32.0f));
    float sn, cs;
    sincosf(pos * theta, &sn, &cs);

    float* b = g_qkv + (size_t)t * QKV_DIM + col0;
    const float x0 = b[0], x1 = b[1];
    b[0] = x0 * cs - x1 * sn;
    b[1] = x1 * cs + x0 * sn;
}

// =======================================================================
// Flash attention, tf32 mma.sync, kv-block 64 (round-11 structure with
// prefetch-ahead preserved). g_qkv PRE-ROUNDED to tf32:
//  - Q/K/V smem fills are pure copies (no cvt); scale folded into softmax.
//  - K prefetch via cp.async into the NEXT ping-pong buffer, issued right
//    after the barrier so the copy overlaps this block's MMA work.
//  - V keeps the register-prefetch gather (strided; permuted for P-in-reg).
//  - one __syncthreads per iteration; LPT launch order.
// =======================================================================
#define ABM 128
#define ABN 64
#define AQ_BYTES  (ABM * 528)
#define AK_BYTES  (ABN * 528)
#define AVT_BYTES (HEAD_DIM * ABN * 4)
#define ABUF_B    (AK_BYTES + AVT_BYTES)
#define ATTN_SMEM (AQ_BYTES + 2 * ABUF_B)

__global__ __launch_bounds__(256)
void attn_tc(uint32_t* __restrict__ chi, uint32_t* __restrict__ clo)
{
    extern __shared__ __align__(1024) char sraw[];
    const uint32_t sb = smem_u32(sraw);
    const uint32_t qb = sb;

    const int head = blockIdx.x;
    const int mb   = gridDim.y - 1 - blockIdx.y;   // LPT
    const int tid  = threadIdx.x;
    const int lane = tid & 31;
    const int wid  = tid >> 5;
    const int r    = lane >> 2;
    const int c    = lane & 3;
    const int rb   = wid * 16;
    const int g    = head / GQA_REP;
    const float scale = 0.08838834764831845f;      // 1/sqrt(128)

    const int lrow  = ((lane >> 3) & 1) * 8 + (lane & 7);
    const int lchk  = (lane >> 4) * 16;
    const int brow  = ((lane >> 4) & 1) * 8 + (lane & 7);
    const int bchk  = ((lane >> 3) & 1) * 16;

    // K fill unit mapping (shared by issue sites): 64 rows x 32 chunks,
    // 2048 chunks / 256 threads = 8 per thread; warp-contiguous chunks.
    const int krow0 = tid >> 5;          // +8*u rows
    const int kch   = tid & 31;

    // ---- Q tile (pre-rounded; plain copy) ----
    for (int i = tid; i < ABM * 32; i += 256) {
        const int row = i >> 5, c4 = (i & 31) << 2;
        const float4 v = *(const float4*)&g_qkv[(size_t)(mb * ABM + row) *
                                                QKV_DIM + head * HEAD_DIM + c4];
        *(float4*)(sraw + (size_t)row * 528 + c4 * 4) = v;
    }

    // ---- issue K(0) cp.async into buffer 0; prefetch V(0) in regs ----
    {
        const uint32_t kb0 = sb + AQ_BYTES;
        #pragma unroll
        for (int u = 0; u < 8; ++u) {
            const int row = krow0 + 8 * u;
            cp16(kb0 + (uint32_t)(row * 528 + kch * 16),
                 g_qkv + (size_t)row * QKV_DIM + Q_SZ + g * HEAD_DIM + kch * 4);
        }
        cp_commit();
    }
    float4 vr[8];
    #pragma unroll
    for (int q = 0; q < 8; ++q) {
        const int i = tid + 256 * q;
        const int d = i & 127, idx = i >> 7, m = idx >> 1, h = idx & 1;
        const float* vbase = g_qkv + Q_SZ + KV_SZ + g * HEAD_DIM + d;
        vr[q].x = vbase[(size_t)(8 * m + h + 0) * QKV_DIM];
        vr[q].y = vbase[(size_t)(8 * m + h + 2) * QKV_DIM];
        vr[q].z = vbase[(size_t)(8 * m + h + 4) * QKV_DIM];
        vr[q].w = vbase[(size_t)(8 * m + h + 6) * QKV_DIM];
    }

    float o[16][4];
    #pragma unroll
    for (int j = 0; j < 16; ++j)
        #pragma unroll
        for (int q = 0; q < 4; ++q) o[j][q] = 0.f;
    float mst0 = -1e30f, mst1 = -1e30f, lst0 = 0.f, lst1 = 0.f;

    const int nbEnd = 2 * mb + 1;
    for (int nb = 0; nb <= nbEnd; ++nb) {
        const uint32_t kbuf  = sb + AQ_BYTES + (uint32_t)(nb & 1) * ABUF_B;
        const uint32_t vtbuf = kbuf + AK_BYTES;

        // ---- store prefetched V into this buffer (pre-rounded values) ----
        #pragma unroll
        for (int q = 0; q < 8; ++q) {
            const int i = tid + 256 * q;
            const int d = i & 127, idx = i >> 7, m = idx >> 1, h = idx & 1;
            const uint32_t off = (uint32_t)d * 256 +
                (((uint32_t)(32 * m + 16 * h)) ^ (((uint32_t)d & 7) << 4));
            *(float4*)(sraw + (vtbuf - sb) + off) = vr[q];
        }
        cp_wait<0>();        // K(nb) landed (this thread's chunks)
        __syncthreads();     // all K/V of this buffer visible; prev reads done

        // ---- issue K(nb+1) into other buffer; prefetch V(nb+1) in regs ----
        if (nb < nbEnd) {
            const uint32_t kbn = sb + AQ_BYTES + (uint32_t)((nb + 1) & 1) * ABUF_B;
            #pragma unroll
            for (int u = 0; u < 8; ++u) {
                const int row = krow0 + 8 * u;
                cp16(kbn + (uint32_t)(row * 528 + kch * 16),
                     g_qkv + (size_t)((nb + 1) * ABN + row) * QKV_DIM + Q_SZ +
                         g * HEAD_DIM + kch * 4);
            }
            cp_commit();
            #pragma unroll
            for (int q = 0; q < 8; ++q) {
                const int i = tid + 256 * q;
                const int d = i & 127, idx = i >> 7, m = idx >> 1, h = idx & 1;
                const float* vbase = g_qkv + (size_t)((nb + 1) * ABN) * QKV_DIM +
                                     Q_SZ + KV_SZ + g * HEAD_DIM + d;
                vr[q].x = vbase[(size_t)(8 * m + h + 0) * QKV_DIM];
                vr[q].y = vbase[(size_t)(8 * m + h + 2) * QKV_DIM];
                vr[q].z = vbase[(size_t)(8 * m + h + 4) * QKV_DIM];
                vr[q].w = vbase[(size_t)(8 * m + h + 6) * QKV_DIM];
            }
        }

        // ---- S = Q K^T (raw, unscaled) ----
        float s[8][4];
        #pragma unroll
        for (int j = 0; j < 8; ++j)
            #pragma unroll
            for (int q = 0; q < 4; ++q) s[j][q] = 0.f;

        #pragma unroll 4
        for (int k0 = 0; k0 < 16; ++k0) {
            uint32_t aq[4];
            ldsm4(aq, qb + (uint32_t)((rb + lrow) * 132 + 8 * k0) * 4 + lchk);
            #pragma unroll
            for (int jp = 0; jp < 4; ++jp) {
                uint32_t kf[4];
                ldsm4(kf, kbuf + (uint32_t)((16 * jp + brow) * 132 + 8 * k0) * 4 + bchk);
                MMA_TF32(s[2 * jp],     aq[0], aq[1], aq[2], aq[3], kf[0], kf[1]);
                MMA_TF32(s[2 * jp + 1], aq[0], aq[1], aq[2], aq[3], kf[2], kf[3]);
            }
        }

        // ---- causal mask ----
        if (nb >= 2 * mb) {
            const int row0 = mb * ABM + rb + r;
            #pragma unroll
            for (int j = 0; j < 8; ++j) {
                const int col = nb * ABN + 8 * j + 2 * c;
                if (col     > row0)     s[j][0] = -1e30f;
                if (col + 1 > row0)     s[j][1] = -1e30f;
                if (col     > row0 + 8) s[j][2] = -1e30f;
                if (col + 1 > row0 + 8) s[j][3] = -1e30f;
            }
        }

        // ---- online softmax (scale folded; scale > 0) ----
        float mx0 = -1e30f, mx1 = -1e30f;
        #pragma unroll
        for (int j = 0; j < 8; ++j) {
            mx0 = fmaxf(mx0, fmaxf(s[j][0], s[j][1]));
            mx1 = fmaxf(mx1, fmaxf(s[j][2], s[j][3]));
        }
        mx0 = fmaxf(mx0, __shfl_xor_sync(0xffffffffu, mx0, 1));
        mx0 = fmaxf(mx0, __shfl_xor_sync(0xffffffffu, mx0, 2));
        mx1 = fmaxf(mx1, __shfl_xor_sync(0xffffffffu, mx1, 1));
        mx1 = fmaxf(mx1, __shfl_xor_sync(0xffffffffu, mx1, 2));
        const float mn0 = fmaxf(mst0, scale * mx0);
        const float mn1 = fmaxf(mst1, scale * mx1);
        const float al0 = __expf(mst0 - mn0), al1 = __expf(mst1 - mn1);
        float sum0 = 0.f, sum1 = 0.f;
        #pragma unroll
        for (int j = 0; j < 8; ++j) {
            s[j][0] = f_tf32(__expf(fmaf(scale, s[j][0], -mn0))); sum0 += s[j][0];
            s[j][1] = f_tf32(__expf(fmaf(scale, s[j][1], -mn0))); sum0 += s[j][1];
            s[j][2] = f_tf32(__expf(fmaf(scale, s[j][2], -mn1))); sum1 += s[j][2];
            s[j][3] = f_tf32(__expf(fmaf(scale, s[j][3], -mn1))); sum1 += s[j][3];
        }
        sum0 += __shfl_xor_sync(0xffffffffu, sum0, 1);
        sum0 += __shfl_xor_sync(0xffffffffu, sum0, 2);
        sum1 += __shfl_xor_sync(0xffffffffu, sum1, 1);
        sum1 += __shfl_xor_sync(0xffffffffu, sum1, 2);
        lst0 = lst0 * al0 + sum0;  mst0 = mn0;
        lst1 = lst1 * al1 + sum1;  mst1 = mn1;
        #pragma unroll
        for (int j = 0; j < 16; ++j) {
            o[j][0] *= al0; o[j][1] *= al0;
            o[j][2] *= al1; o[j][3] *= al1;
        }

        // ---- O += P @ V (P from s-regs; VT rows pre-permuted) ----
        #pragma unroll
        for (int kk = 0; kk < 8; ++kk) {
            const uint32_t a0 = __float_as_uint(s[kk][0]);
            const uint32_t a1 = __float_as_uint(s[kk][2]);
            const uint32_t a2 = __float_as_uint(s[kk][1]);
            const uint32_t a3 = __float_as_uint(s[kk][3]);
            #pragma unroll
            for (int jp = 0; jp < 8; ++jp) {
                const int vrow = 16 * jp + brow;
                const uint32_t addr = vtbuf + (uint32_t)vrow * 256 +
                    (((uint32_t)(kk * 32 + bchk)) ^ (((uint32_t)vrow & 7) << 4));
                uint32_t vf[4];
                ldsm4(vf, addr);
                MMA_TF32(o[2 * jp],     a0, a1, a2, a3, vf[0], vf[1]);
                MMA_TF32(o[2 * jp + 1], a0, a1, a2, a3, vf[2], vf[3]);
            }
        }
    }

    // ---- normalize + write ctx as pre-split bf16 hi/lo planes ----
    const float il0 = 1.0f / lst0, il1 = 1.0f / lst1;
    const int trow = mb * ABM + rb + r;
    #pragma unroll
    for (int j = 0; j < 16; ++j) {
        const int col = head * HEAD_DIM + 8 * j + 2 * c;
        uint32_t h, l;
        bsplit(o[j][0] * il0, o[j][1] * il0, h, l);
        const size_t p0 = ((size_t)trow * HIDDEN + col) >> 1;
        chi[p0] = h; clo[p0] = l;
        bsplit(o[j][2] * il1, o[j][3] * il1, h, l);
        const size_t p1 = ((size_t)(trow + 8) * HIDDEN + col) >> 1;
        chi[p1] = h; clo[p1] = l;
    }
}

// =======================================================================
// host side
// =======================================================================
typedef CUresult (*tmap_encode_fn)(
    CUtensorMap*, CUtensorMapDataType, cuuint32_t, void*,
    const cuuint64_t*, const cuuint64_t*, const cuuint32_t*, const cuuint32_t*,
    CUtensorMapInterleave, CUtensorMapSwizzle, CUtensorMapL2promotion,
    CUtensorMapFloatOOBfill);

static tmap_encode_fn get_encoder()
{
    void* p = nullptr;
    cudaDriverEntryPointQueryResult qr;
#if CUDART_VERSION >= 12050
    cudaGetDriverEntryPointByVersion("cuTensorMapEncodeTiled", &p, 12000,
                                     cudaEnableDefault, &qr);
#else
    cudaGetDriverEntryPoint("cuTensorMapEncodeTiled", &p, cudaEnableDefault, &qr);
#endif
    return (tmap_encode_fn)p;
}

static void make_map(tmap_encode_fn enc, CUtensorMap* m, void* ptr,
                     uint64_t inner, uint64_t rows)
{
    cuuint64_t dims[2]    = {inner, rows};
    cuuint64_t strides[1] = {inner * 4};
    cuuint32_t box[2]     = {32, 128};
    cuuint32_t es[2]      = {1, 1};
    enc(m, CU_TENSOR_MAP_DATA_TYPE_FLOAT32, 2, ptr, dims, strides, box, es,
        CU_TENSOR_MAP_INTERLEAVE_NONE, CU_TENSOR_MAP_SWIZZLE_128B,
        CU_TENSOR_MAP_L2_PROMOTION_L2_128B, CU_TENSOR_MAP_FLOAT_OOB_FILL_NONE);
}

extern "C" void kernel_launch(void* const* d_in, const int* in_sizes, int n_in,
                              void* d_out, int out_size)
{
    const int*   positions = (const int*)d_in[0];
    const float* hidden    = (const float*)d_in[1];
    const float* w_qkv     = (const float*)d_in[2];
    const float* b_qkv     = (const float*)d_in[3];
    const float* w_dense   = (const float*)d_in[4];
    float*       out       = (float*)d_out;

    float *qkv_p, *arnd, *bt;
    uint32_t *ahi, *alo, *bhi2, *blo2;
    cudaGetSymbolAddress((void**)&qkv_p, g_qkv);
    cudaGetSymbolAddress((void**)&arnd,  g_arnd);
    cudaGetSymbolAddress((void**)&bt,    g_bt);
    cudaGetSymbolAddress((void**)&ahi,   g_ahi);
    cudaGetSymbolAddress((void**)&alo,   g_alo);
    cudaGetSymbolAddress((void**)&bhi2,  g_bhi2);
    cudaGetSymbolAddress((void**)&blo2,  g_blo2);

    tmap_encode_fn enc = get_encoder();
    CUtensorMap mA, mB, mAhi, mAlo, mBhi2, mBlo2;
    make_map(enc, &mA,    arnd, HIDDEN, T_SEQ);
    make_map(enc, &mB,    bt,   HIDDEN, QKV_DIM);
    make_map(enc, &mAhi,  ahi,  K2DIM,  T_SEQ);
    make_map(enc, &mAlo,  alo,  K2DIM,  T_SEQ);
    make_map(enc, &mBhi2, bhi2, K2DIM,  HIDDEN);
    make_map(enc, &mBlo2, blo2, K2DIM,  HIDDEN);

    cudaFuncSetAttribute(gemm_tf32,
                         cudaFuncAttributeMaxDynamicSharedMemorySize, GEMM_SMEM);
    cudaFuncSetAttribute(gemm_bf16x3,
                         cudaFuncAttributeMaxDynamicSharedMemorySize, GEMM_SMEM);
    cudaFuncSetAttribute(attn_tc,
                         cudaFuncAttributeMaxDynamicSharedMemorySize, ATTN_SMEM);

    // 1) prep passes
    round_copy<<<(T_SEQ * HIDDEN / 4 + 255) / 256, 256>>>(
        (const float4*)hidden, (float4*)arnd, T_SEQ * HIDDEN / 4);
    transpose_round<<<dim3(QKV_DIM / 32, HIDDEN / 32), dim3(32, 8)>>>(
        w_qkv, bt, HIDDEN, QKV_DIM);
    split_bmat_t<<<dim3(HIDDEN / 32, K2DIM / 32), dim3(32, 8)>>>(
        w_dense, bhi2, blo2, K2DIM, HIDDEN);

    // 2) QKV = hidden @ w_qkv + b_qkv   (tf32 tensor cores)
    gemm_tf32<<<dim3(QKV_DIM / 256, T_SEQ / 128), 512, GEMM_SMEM>>>(
        mA, mB, b_qkv, qkv_p, QKV_DIM);

    // 3) RoPE in place, then round all of qkv to tf32 (idempotent)
    const int totalRope = T_SEQ * NUM_HEADS * 32 + T_SEQ * KV_GROUPS * 32;
    rope_kernel<<<(totalRope + 255) / 256, 256>>>(positions);
    round_inplace<<<(T_SEQ * QKV_DIM / 4 + 255) / 256, 256>>>(
        (float4*)qkv_p, T_SEQ * QKV_DIM / 4);

    // 4) attention -> ctx hi/lo planes
    attn_tc<<<dim3(NUM_HEADS, T_SEQ / ABM), 256, ATTN_SMEM>>>(ahi, alo);

    // 5) out = ctx @ w_dense   (bf16x3 tensor cores)
    gemm_bf16x3<<<dim3(HIDDEN / 256, T_SEQ / 128), 512, GEMM_SMEM>>>(
        mAhi, mAlo, mBhi2, mBlo2, out, HIDDEN);
}